// round 10
// baseline (speedup 1.0000x reference)
#include <cuda_runtime.h>
#include <cuda_bf16.h>

// AlphaRotatedIoULoss: loss = mean(1 - max(IoU_rot, 1e-6)^3) over N rotated-box pairs.
// Round 10 (resubmit of round 9 after infra failure): fused single kernel, TWO
// pairs per thread (independent clip pipelines interleave to fill issue gaps),
// float2 vectorized loads (5x LDG.64 per tensor per thread instead of 10x LDG.32).

#define MAX_BLOCKS 16384
static __device__ float g_part[MAX_BLOCKS];
static __device__ unsigned int g_cnt = 0;   // wraps back to 0 every launch

__device__ __forceinline__ float safe_inv(float dx) {
    float dxs = (fabsf(dx) > 1e-12f) ? dx : copysignf(1e-12f, dx);
    return __fdividef(1.0f, dxs);
}

// Clip edge (sx,sy)->(vx,vy) against slab -W <= x <= W; inv = 1/dx (clamped).
// Emits two points: the clamped inside sub-segment, or (if fully outside one
// side) both endpoints projected onto that boundary line. Collinear points on
// the clip line are shoelace-neutral, so no compaction is needed.
__device__ __forceinline__ void slab_edge(
    float sx, float sy, float vx, float vy, float inv, float W,
    float& ax, float& ay, float& bx, float& by)
{
    float dx = vx - sx;
    float dy = vy - sy;
    float tA = (-W - sx) * inv;
    float tB = ( W - sx) * inv;
    float tmin = fminf(tA, tB);
    float tmax = fmaxf(tA, tB);
    float t0 = fmaxf(tmin, 0.0f);
    float t1 = fminf(tmax, 1.0f);
    bool empty = (t0 > t1);              // edge entirely outside, one side
    float pW = copysignf(W, sx);         // shared projected x for the empty case
    ax = empty ? pW : fmaf(t0, dx, sx);
    ay = empty ? sy : fmaf(t0, dy, sy);
    bx = empty ? pW : fmaf(t1, dx, sx);
    by = empty ? vy : fmaf(t1, dy, sy);
}

// Full per-pair loss from the 10 box parameters.
__device__ __forceinline__ float pair_loss(
    float x1, float y1, float w1, float h1, float a1,
    float x2, float y2, float w2, float h2, float a2)
{
    float s2f, c2f, s1f, c1f;
    __sincosf(a2, &s2f, &c2f);
    __sincosf(a1, &s1f, &c1f);

    // Box1 center in box2's local frame.
    float rx = x1 - x2, ry = y1 - y2;
    float lx =  rx * c2f + ry * s2f;
    float ly = -rx * s2f + ry * c2f;

    // Relative rotation.
    float c = c1f * c2f + s1f * s2f;
    float s = s1f * c2f - c1f * s2f;

    float hw1 = 0.5f * w1, hh1 = 0.5f * h1;
    float W = 0.5f * w2,  H = 0.5f * h2;

    float wx = hw1 * c, wy = hw1 * s;
    float hx = -hh1 * s, hy = hh1 * c;

    // Box1 corners (CCW) in box2 frame.
    float kx[4], ky[4];
    kx[0] = lx - wx - hx;  ky[0] = ly - wy - hy;
    kx[1] = lx + wx - hx;  ky[1] = ly + wy - hy;
    kx[2] = lx + wx + hx;  ky[2] = ly + wy + hy;
    kx[3] = lx - wx + hx;  ky[3] = ly - wy + hy;

    // Stage 1: clip against |x| <= W. Antiparallel edge pairs -> 2 RCPs.
    float inv01 = safe_inv(kx[1] - kx[0]);
    float inv12 = safe_inv(kx[2] - kx[1]);
    float einv[4] = { inv01, inv12, -inv01, -inv12 };

    float Px[8], Py[8];
    #pragma unroll
    for (int e = 0; e < 4; e++) {
        int e1 = (e + 1) & 3;
        slab_edge(kx[e], ky[e], kx[e1], ky[e1], einv[e], W,
                  Px[2 * e], Py[2 * e], Px[2 * e + 1], Py[2 * e + 1]);
    }

    // Stage 2: clip against |y| <= H with fused shoelace accumulation.
    float acc = 0.0f;
    float a0x = 0.0f, a0y = 0.0f;
    float pbx = 0.0f, pby = 0.0f;
    #pragma unroll
    for (int e = 0; e < 8; e++) {
        int e1 = (e + 1) & 7;
        float ax, ay, bx, by;
        float iv = safe_inv(Py[e1] - Py[e]);
        slab_edge(Py[e], Px[e], Py[e1], Px[e1], iv, H, ay, ax, by, bx);
        if (e == 0) { a0x = ax; a0y = ay; }
        else        { acc += pbx * ay - ax * pby; }
        acc += ax * by - bx * ay;
        pbx = bx; pby = by;
    }
    acc += pbx * a0y - a0x * pby;

    float inter = 0.5f * fabsf(acc);
    float area1 = w1 * h1;
    float area2 = w2 * h2;
    float iou = __fdividef(inter, area1 + area2 - inter);
    iou = fmaxf(iou, 1e-6f);
    return 1.0f - iou * iou * iou;
}

__global__ __launch_bounds__(256) void arl_fused_kernel(
    const float* __restrict__ pred,
    const float* __restrict__ tgt,
    float* __restrict__ out,
    int n, float inv_n)
{
    int tid = threadIdx.x;
    int gid = blockIdx.x * 256 + tid;
    int i0 = gid * 2;                    // this thread owns pairs i0, i0+1
    float loss = 0.0f;

    if (i0 + 1 < n) {
        // 80B per tensor per thread starting at float offset 10*gid; the base
        // pointers are allocator-aligned (>=256B) and 10*gid*4 is a multiple
        // of 8 -> float2 loads are always 8B-aligned.
        const float2* p2 = reinterpret_cast<const float2*>(pred + 10 * gid);
        const float2* t2 = reinterpret_cast<const float2*>(tgt + 10 * gid);
        float2 pa = __ldg(p2 + 0), pb = __ldg(p2 + 1), pc = __ldg(p2 + 2),
               pd = __ldg(p2 + 3), pe = __ldg(p2 + 4);
        float2 ta = __ldg(t2 + 0), tb = __ldg(t2 + 1), tc = __ldg(t2 + 2),
               td = __ldg(t2 + 3), te = __ldg(t2 + 4);

        // Pair A: floats 0..4 ; Pair B: floats 5..9.
        float lA = pair_loss(pa.x, pa.y, pb.x, pb.y, pc.x,
                             ta.x, ta.y, tb.x, tb.y, tc.x);
        float lB = pair_loss(pc.y, pd.x, pd.y, pe.x, pe.y,
                             tc.y, td.x, td.y, te.x, te.y);
        loss = lA + lB;
    } else if (i0 < n) {
        const float* p = pred + 5 * i0;
        const float* t = tgt + 5 * i0;
        loss = pair_loss(__ldg(p + 0), __ldg(p + 1), __ldg(p + 2),
                         __ldg(p + 3), __ldg(p + 4),
                         __ldg(t + 0), __ldg(t + 1), __ldg(t + 2),
                         __ldg(t + 3), __ldg(t + 4));
    }

    // Block reduction.
    __shared__ float wsum[8];
    __shared__ bool s_last;
    #pragma unroll
    for (int off = 16; off > 0; off >>= 1)
        loss += __shfl_down_sync(0xffffffffu, loss, off);
    int lane = tid & 31;
    int wid  = tid >> 5;
    if (lane == 0) wsum[wid] = loss;
    __syncthreads();
    if (wid == 0) {
        float v = (lane < 8) ? wsum[lane] : 0.0f;
        #pragma unroll
        for (int off = 4; off > 0; off >>= 1)
            v += __shfl_down_sync(0xffu, v, off);
        if (lane == 0) {
            g_part[blockIdx.x] = v;
            __threadfence();
            // atomicInc wraps to 0 after gridDim.x increments -> counter ends
            // every launch at 0 (graph-replay deterministic).
            unsigned int old = atomicInc(&g_cnt, gridDim.x - 1);
            s_last = (old == gridDim.x - 1);
        }
    }
    __syncthreads();

    // Last block reduces the per-block partials and writes the mean.
    if (s_last) {
        double v = 0.0;
        for (int j = tid; j < gridDim.x; j += 256)
            v += (double)g_part[j];
        #pragma unroll
        for (int off = 16; off > 0; off >>= 1)
            v += __shfl_down_sync(0xffffffffu, v, off);
        __shared__ double dsum[8];
        if (lane == 0) dsum[wid] = v;
        __syncthreads();
        if (wid == 0) {
            double d = (lane < 8) ? dsum[lane] : 0.0;
            #pragma unroll
            for (int off = 4; off > 0; off >>= 1)
                d += __shfl_down_sync(0xffu, d, off);
            if (lane == 0)
                out[0] = (float)(d * (double)inv_n);
        }
    }
}

extern "C" void kernel_launch(void* const* d_in, const int* in_sizes, int n_in,
                              void* d_out, int out_size)
{
    const float* pred = (const float*)d_in[0];
    const float* tgt  = (const float*)d_in[1];
    float* out = (float*)d_out;
    int n = in_sizes[0] / 5;

    int pairs_per_block = 512;           // 256 threads x 2 pairs
    int blocks = (n + pairs_per_block - 1) / pairs_per_block;
    if (blocks > MAX_BLOCKS) blocks = MAX_BLOCKS;   // N=1e6 -> 1954, fits
    arl_fused_kernel<<<blocks, 256>>>(pred, tgt, out, n, 1.0f / (float)n);
}

// round 11
// speedup vs baseline: 1.3200x; 1.3200x over previous
#include <cuda_runtime.h>
#include <cuda_bf16.h>

// AlphaRotatedIoULoss: loss = mean(1 - max(IoU_rot, 1e-6)^3) over N rotated-box pairs.
// Round 11: Green's-theorem clipped-edge area. In box2's frame (axis-aligned
// slab [-W,W]x[-H,H]), area(P1 ∩ box) = ∮ x dy over the clipped polygon.
//   * runs along y=±H contribute 0 (dy=0)
//   * runs along x=±W telescope to ±W·Δclamp(y) per outside sub-interval
// so each of box1's 4 edges contributes independently:
//   interior = dy·(t1-t0)·x((t0+t1)/2)  over t ∈ [x-interval] ∩ [y-interval]
//   boundary = XH·[(clamp(vy)-clamp(y(tx1))) - (clamp(y(tx0))-clamp(sy))]
// No point arrays, no clip cascade, no shoelace chain.

#define MAX_BLOCKS 16384
static __device__ float g_part[MAX_BLOCKS];
static __device__ unsigned int g_cnt = 0;   // wraps back to 0 every launch

__device__ __forceinline__ float safe_inv(float dx) {
    // Antisymmetric: safe_inv(-x) == -safe_inv(x) exactly (incl. ±0).
    float dxs = (fabsf(dx) > 1e-12f) ? dx : copysignf(1e-12f, dx);
    return __fdividef(1.0f, dxs);
}

__device__ __forceinline__ float clampf(float v, float lo, float hi) {
    return fminf(fmaxf(v, lo), hi);
}

// Contribution of one polygon edge (sx,sy)->(sx+dx, sy+dy) to ∮x dy of the
// polygon clipped to [-W,W]x[-H,H]. hdx = 0.5*dx; inv_dx/inv_dy precomputed.
// csy/cvy are the y-clamped endpoint y's.
__device__ __forceinline__ float edge_contrib(
    float sx, float sy, float dx, float dy,
    float hdx, float inv_dx, float inv_dy,
    float csy, float cvy, float W, float H)
{
    // x-slab crossing interval [tx0, tx1] ⊂ [0,1]
    float tA = (-W - sx) * inv_dx;
    float tB = ( W - sx) * inv_dx;
    float tx0 = clampf(fminf(tA, tB), 0.0f, 1.0f);
    float tx1 = clampf(fmaxf(tA, tB), 0.0f, 1.0f);

    // y at the x-interval endpoints (for the boundary runs)
    float y0 = fmaf(tx0, dy, sy);
    float y1 = fmaf(tx1, dy, sy);

    // interior: intersect the y-crossing interval with [tx0, tx1]
    float uA = (-H - sy) * inv_dy;
    float uB = ( H - sy) * inv_dy;
    float t0 = clampf(fminf(uA, uB), tx0, tx1);
    float t1 = clampf(fmaxf(uA, uB), tx0, tx1);
    float xm = fmaf(hdx, t0 + t1, sx);           // x at midpoint of [t0,t1]
    float interior = dy * (t1 - t0) * xm;

    // boundary: low-t outside run at x = -XH, high-t run at x = +XH
    float XH  = copysignf(W, dx);
    float cy0 = clampf(y0, -H, H);
    float cy1 = clampf(y1, -H, H);
    return fmaf(XH, (cvy - cy1) - (cy0 - csy), interior);
}

// Full per-pair loss from the 10 box parameters.
__device__ __forceinline__ float pair_loss(
    float x1, float y1, float w1, float h1, float a1,
    float x2, float y2, float w2, float h2, float a2)
{
    float s2f, c2f, s1f, c1f;
    __sincosf(a2, &s2f, &c2f);
    __sincosf(a1, &s1f, &c1f);

    // Box1 center in box2's local frame.
    float rx = x1 - x2, ry = y1 - y2;
    float lx =  rx * c2f + ry * s2f;
    float ly = -rx * s2f + ry * c2f;

    // Relative rotation.
    float c = c1f * c2f + s1f * s2f;
    float s = s1f * c2f - c1f * s2f;

    float hw1 = 0.5f * w1, hh1 = 0.5f * h1;
    float W = 0.5f * w2,  H = 0.5f * h2;

    float wx = hw1 * c, wy = hw1 * s;
    float hx = -hh1 * s, hy = hh1 * c;

    // Box1 corners (CCW) in box2 frame.
    float kx0 = lx - wx - hx, ky0 = ly - wy - hy;
    float kx1 = lx + wx - hx, ky1 = ly + wy - hy;
    float kx2 = lx + wx + hx, ky2 = ly + wy + hy;
    float kx3 = lx - wx + hx, ky3 = ly - wy + hy;

    // Edge vectors; central symmetry: edge2 = -edge0, edge3 = -edge1.
    float dx0 = kx1 - kx0, dy0 = ky1 - ky0;
    float dx1 = kx2 - kx1, dy1 = ky2 - ky1;
    float ix0 = safe_inv(dx0), iy0 = safe_inv(dy0);
    float ix1 = safe_inv(dx1), iy1 = safe_inv(dy1);
    float hdx0 = 0.5f * dx0, hdx1 = 0.5f * dx1;

    // Clamped corner y's (boundary-run endpoints).
    float cy0 = clampf(ky0, -H, H);
    float cy1 = clampf(ky1, -H, H);
    float cy2 = clampf(ky2, -H, H);
    float cy3 = clampf(ky3, -H, H);

    float acc;
    acc  = edge_contrib(kx0, ky0,  dx0,  dy0,  hdx0,  ix0,  iy0, cy0, cy1, W, H);
    acc += edge_contrib(kx1, ky1,  dx1,  dy1,  hdx1,  ix1,  iy1, cy1, cy2, W, H);
    acc += edge_contrib(kx2, ky2, -dx0, -dy0, -hdx0, -ix0, -iy0, cy2, cy3, W, H);
    acc += edge_contrib(kx3, ky3, -dx1, -dy1, -hdx1, -ix1, -iy1, cy3, cy0, W, H);

    float inter = fabsf(acc);
    float area1 = w1 * h1;
    float area2 = w2 * h2;
    float iou = __fdividef(inter, area1 + area2 - inter);
    iou = fmaxf(iou, 1e-6f);
    return 1.0f - iou * iou * iou;
}

__global__ __launch_bounds__(256) void arl_fused_kernel(
    const float* __restrict__ pred,
    const float* __restrict__ tgt,
    float* __restrict__ out,
    int n, float inv_n)
{
    int tid = threadIdx.x;
    int gid = blockIdx.x * 256 + tid;
    int i0 = gid * 2;                    // this thread owns pairs i0, i0+1
    float loss = 0.0f;

    if (i0 + 1 < n) {
        // 80B per tensor per thread; base allocator-aligned, offset 8B-aligned.
        const float2* p2 = reinterpret_cast<const float2*>(pred + 10 * gid);
        const float2* t2 = reinterpret_cast<const float2*>(tgt + 10 * gid);
        float2 pa = __ldg(p2 + 0), pb = __ldg(p2 + 1), pc = __ldg(p2 + 2),
               pd = __ldg(p2 + 3), pe = __ldg(p2 + 4);
        float2 ta = __ldg(t2 + 0), tb = __ldg(t2 + 1), tc = __ldg(t2 + 2),
               td = __ldg(t2 + 3), te = __ldg(t2 + 4);

        float lA = pair_loss(pa.x, pa.y, pb.x, pb.y, pc.x,
                             ta.x, ta.y, tb.x, tb.y, tc.x);
        float lB = pair_loss(pc.y, pd.x, pd.y, pe.x, pe.y,
                             tc.y, td.x, td.y, te.x, te.y);
        loss = lA + lB;
    } else if (i0 < n) {
        const float* p = pred + 5 * i0;
        const float* t = tgt + 5 * i0;
        loss = pair_loss(__ldg(p + 0), __ldg(p + 1), __ldg(p + 2),
                         __ldg(p + 3), __ldg(p + 4),
                         __ldg(t + 0), __ldg(t + 1), __ldg(t + 2),
                         __ldg(t + 3), __ldg(t + 4));
    }

    // Block reduction.
    __shared__ float wsum[8];
    __shared__ bool s_last;
    #pragma unroll
    for (int off = 16; off > 0; off >>= 1)
        loss += __shfl_down_sync(0xffffffffu, loss, off);
    int lane = tid & 31;
    int wid  = tid >> 5;
    if (lane == 0) wsum[wid] = loss;
    __syncthreads();
    if (wid == 0) {
        float v = (lane < 8) ? wsum[lane] : 0.0f;
        #pragma unroll
        for (int off = 4; off > 0; off >>= 1)
            v += __shfl_down_sync(0xffu, v, off);
        if (lane == 0) {
            g_part[blockIdx.x] = v;
            __threadfence();
            // atomicInc wraps to 0 after gridDim.x increments -> counter ends
            // every launch at 0 (graph-replay deterministic).
            unsigned int old = atomicInc(&g_cnt, gridDim.x - 1);
            s_last = (old == gridDim.x - 1);
        }
    }
    __syncthreads();

    // Last block reduces the per-block partials and writes the mean.
    if (s_last) {
        double v = 0.0;
        for (int j = tid; j < gridDim.x; j += 256)
            v += (double)g_part[j];
        #pragma unroll
        for (int off = 16; off > 0; off >>= 1)
            v += __shfl_down_sync(0xffffffffu, v, off);
        __shared__ double dsum[8];
        if (lane == 0) dsum[wid] = v;
        __syncthreads();
        if (wid == 0) {
            double d = (lane < 8) ? dsum[lane] : 0.0;
            #pragma unroll
            for (int off = 4; off > 0; off >>= 1)
                d += __shfl_down_sync(0xffu, d, off);
            if (lane == 0)
                out[0] = (float)(d * (double)inv_n);
        }
    }
}

extern "C" void kernel_launch(void* const* d_in, const int* in_sizes, int n_in,
                              void* d_out, int out_size)
{
    const float* pred = (const float*)d_in[0];
    const float* tgt  = (const float*)d_in[1];
    float* out = (float*)d_out;
    int n = in_sizes[0] / 5;

    int pairs_per_block = 512;           // 256 threads x 2 pairs
    int blocks = (n + pairs_per_block - 1) / pairs_per_block;
    if (blocks > MAX_BLOCKS) blocks = MAX_BLOCKS;   // N=1e6 -> 1954, fits
    arl_fused_kernel<<<blocks, 256>>>(pred, tgt, out, n, 1.0f / (float)n);
}